// round 17
// baseline (speedup 1.0000x reference)
#include <cuda_runtime.h>
#include <math.h>
#include <stdint.h>

#define Bq 256
#define Sq 512
#define Iq 128
#define Hq 256
#define CPG 16      // CTAs per group
#define NGRP 8      // groups
#define GB 32       // batches per group
#define NCTA 128
#define NTHR 512

typedef unsigned long long u64;

// ---- global scratch ----
__device__ float d_enc[(size_t)Sq * Bq * Hq];   // [S][B][H]
__device__ float d_scores[Bq * Iq];             // reused every step -> L1-bypass access
__device__ int   g_cnt[NGRP];
__device__ int   g_phase[NGRP];

// ------------------------------- helpers -----------------------------------
__device__ __forceinline__ int ld_acq(const int* p) {
    int v;
    asm volatile("ld.acquire.gpu.b32 %0, [%1];" : "=r"(v) : "l"(p) : "memory");
    return v;
}
__device__ __forceinline__ int atom_add_release(int* p, int v) {
    int old;
    asm volatile("atom.release.gpu.global.add.s32 %0, [%1], %2;"
                 : "=r"(old) : "l"(p), "r"(v) : "memory");
    return old;
}
__device__ __forceinline__ void red_release_add(int* p, int v) {
    asm volatile("red.release.gpu.global.add.s32 [%0], %1;" :: "l"(p), "r"(v) : "memory");
}
__device__ __forceinline__ void st_relaxed(int* p, int v) {
    asm volatile("st.relaxed.gpu.global.s32 [%0], %1;" :: "l"(p), "r"(v) : "memory");
}
__device__ __forceinline__ void fma2(u64& d, u64 a, u64 b) {
    asm("fma.rn.f32x2 %0, %1, %2, %0;" : "+l"(d) : "l"(a), "l"(b));
}
__device__ __forceinline__ u64 dupf(float f) {            // {f, f}
    u64 r;
    asm("mov.b64 %0, {%1,%1};" : "=l"(r) : "f"(f));
    return r;
}
__device__ __forceinline__ u64 addf2(u64 a, u64 b) {      // packed f32x2 add
    u64 d;
    asm("add.rn.f32x2 %0, %1, %2;" : "=l"(d) : "l"(a), "l"(b));
    return d;
}
__device__ __forceinline__ u64 shflx16(u64 v) {
    return (u64)__shfl_xor_sync(0xffffffffu, (unsigned long long)v, 16);
}
__device__ __forceinline__ float fsig(float x)  { return 1.f / (1.f + __expf(-x)); }
__device__ __forceinline__ float ftanh(float x) { return 1.f - 2.f / (__expf(2.f * x) + 1.f); }

// Fence-free group barrier pieces (validated R11-R16). Caller supplies the
// surrounding __syncthreads; arrive/wait split lets us hide work under the poll.
__device__ __forceinline__ void gb_arrive(int g, int& want) {
    want++;
    int old = atom_add_release(&g_cnt[g], 1);
    if (old == CPG - 1) {
        st_relaxed(&g_cnt[g], 0);
        red_release_add(&g_phase[g], 1);
    }
}
__device__ __forceinline__ void gb_wait(int g, int want) {
    while (ld_acq(&g_phase[g]) < want) { }
}

// SMEM layout (float offsets, all even). Activations are batch-pair packed:
//   h  u64 at [k*17 + (k>>4) + p]  = {h[k][p], h[k][p+16]}
//   x  u64 at [k*17 + (k>>3) + p]  = {x[k][p], x[k][p+16]}
// Whh is PRE-DUPLICATED: u64 {w,w} at [row*256 + k] -> one 16B broadcast LDS
// feeds 2 fma2 with no dup movs.
// psc aliases GISB[0:256 u64], psx aliases GISA[0:256 u64] (lifetime-disjoint:
// psc: P1-write -> finalize-read -> clobbered by P3 (dead);
// psx: written under h-barrier AFTER gates' last gis read, consumed at next
// step's finalize BEFORE P3 rewrites gis).
#define O_WHHD 0        // 48*256 u64 = 24576 floats (pre-dup'd)
#define O_WIH  24576    // 48*128 = 6144
#define O_WAH  30720    // 8*256  = 2048
#define O_WAX  32768    // 8*128  = 1024
#define O_BA   33792    // 8
#define O_BIH  33800    // 48
#define O_BHH  33848    // 48
#define O_HS   33896    // 4368 u64 = 8736 floats
#define O_XTS  42632    // 2192 u64 = 4384
#define O_XWS  47016    // 4384
#define O_GISA 51400    // 816 u64 = 1632   (psx aliases first 256 u64)
#define O_GISB 53032    // 1632             (psc aliases first 256 u64)
#define O_GHSA 54664    // 1632
#define O_GHSB 56296    // 1632
#define O_RED  57928    // 32
#define SMEM_FLOATS 57960   // 231,840 bytes  (cap 232,448)

#define HIDX(k,b) ((((k)*17 + ((k)>>4) + ((b)&15))*2) + ((b)>>4))
#define XIDX(k,b) ((((k)*17 + ((k)>>3) + ((b)&15))*2) + ((b)>>4))

extern "C" __global__ void __launch_bounds__(NTHR)
da_rnn_kernel(const float* __restrict__ x,
              const float* __restrict__ W_a,  const float* __restrict__ b_a,
              const float* __restrict__ W_ih, const float* __restrict__ b_ih,
              const float* __restrict__ W_hh, const float* __restrict__ b_hh,
              const float* __restrict__ W_t,  const float* __restrict__ b_t,
              const float* __restrict__ W_f,  const float* __restrict__ b_f,
              float* __restrict__ out)
{
    extern __shared__ float sm[];
    float* Wih_s = sm + O_WIH;
    float* Wah_s = sm + O_WAH;
    float* Wax_s = sm + O_WAX;
    float* ba_s  = sm + O_BA;
    float* bih_s = sm + O_BIH;
    float* bhh_s = sm + O_BHH;
    float* hsf   = sm + O_HS;
    float* xtf   = sm + O_XTS;
    float* xwf   = sm + O_XWS;
    float* gisAf = sm + O_GISA;
    float* gisBf = sm + O_GISB;
    float* ghsAf = sm + O_GHSA;
    float* ghsBf = sm + O_GHSB;
    float* red   = sm + O_RED;
    const u64* hs64 = (const u64*)hsf;
    const u64* xt64 = (const u64*)xtf;
    const u64* xw64 = (const u64*)xwf;
    u64* gisA64 = (u64*)gisAf;
    u64* gisB64 = (u64*)gisBf;
    u64* ghsA64 = (u64*)ghsAf;
    u64* ghsB64 = (u64*)ghsBf;
    u64* psx64  = gisA64;                 // alias (see layout note)
    u64* psc64  = gisB64;                 // alias

    const int tid  = threadIdx.x;
    const int grp  = blockIdx.x >> 4;
    const int rr   = blockIdx.x & 15;
    const int gb0  = grp * GB;
    const int lane = tid & 31;
    const int wrp  = tid >> 5;            // 0..15
    const int sub  = lane >> 4;           // K sub-half within warp
    const int p    = lane & 15;           // batch-pair index
    const int rg   = wrp >> 1;            // row group / score row 0..7
    const int ksel = wrp & 1;             // K half

    // ---- load weight slice into SMEM ----
    for (int i = tid; i < 48 * 256; i += NTHR) {          // Whh pre-dup'd
        int l = i >> 8, k = i & 255;
        int grow = (l >> 4) * Hq + 16 * rr + (l & 15);
        float w = W_hh[grow * Hq + k];
        sm[2 * i]     = w;
        sm[2 * i + 1] = w;
    }
    for (int i = tid; i < 48 * 128; i += NTHR) {
        int l = i >> 7, k = i & 127;
        int grow = (l >> 4) * Hq + 16 * rr + (l & 15);
        Wih_s[i] = W_ih[grow * Iq + k];
    }
    for (int i = tid; i < 8 * 256; i += NTHR) {
        int r = i >> 8, k = i & 255;
        Wah_s[i] = W_a[(8 * rr + r) * 384 + 128 + k];
    }
    for (int i = tid; i < 8 * 128; i += NTHR) {
        int r = i >> 7, k = i & 127;
        Wax_s[i] = W_a[(8 * rr + r) * 384 + k];
    }
    if (tid < 8) ba_s[tid] = b_a[8 * rr + tid];
    if (tid < 48) {
        int grow = (tid >> 4) * Hq + 16 * rr + (tid & 15);
        bih_s[tid] = b_ih[grow];
        bhh_s[tid] = b_hh[grow];
    }

    int want = 0;
    if (tid == 0) want = ld_acq(&g_phase[grp]);

    // ---- x pipeline: thread owns (batch pb, k-range pk..pk+7) ----
    const int pb = tid >> 4;            // 0..31
    const int pk = (tid & 15) * 8;      // 0..120
    const float* xrow = x + ((size_t)(gb0 + pb) * Sq) * Iq + pk;

    // prologue: xtf <- x(0); px <- x(1)
    {
        float4 a0 = *(const float4*)(xrow);
        float4 a1 = *(const float4*)(xrow + 4);
        const float v[8] = {a0.x, a0.y, a0.z, a0.w, a1.x, a1.y, a1.z, a1.w};
        #pragma unroll
        for (int j = 0; j < 8; j++) xtf[XIDX(pk + j, pb)] = v[j];
    }
    float4 pxa = *(const float4*)(xrow + (size_t)Iq);
    float4 pxb = *(const float4*)(xrow + (size_t)Iq + 4);
    __syncthreads();

    // prologue psx(0): score x-part for t=0
    {
        const int kq = ksel * 64 + sub * 32;
        const float* wax = Wax_s + rg * 128;
        u64 xacc = 0ull;
        #pragma unroll 4
        for (int i = 0; i < 16; i++) {
            int k = kq + 2 * i;
            u64 x0 = xt64[k * 17 + (k >> 3) + p];
            u64 x1 = xt64[(k + 1) * 17 + ((k + 1) >> 3) + p];
            float2 f = *(const float2*)(wax + k);
            fma2(xacc, dupf(f.x), x0);
            fma2(xacc, dupf(f.y), x1);
        }
        xacc = addf2(xacc, shflx16(xacc));
        if (sub == 0) psx64[wrp * 16 + p] = xacc;
    }

    // ================= recurrent loop =================
    for (int t = 0; t < Sq; t++) {
        // ---- stage h(t-1) into batch-pair SMEM ----
        if (t == 0) {
            for (int i = tid; i < 8736; i += NTHR) hsf[i] = 0.f;
        } else {
            const int b2 = tid >> 4;
            const int u0 = (tid & 15) * 16;
            const float* ep = d_enc + (size_t)(t - 1) * Bq * Hq + (size_t)(gb0 + b2) * Hq + u0;
            float4 h0 = *(const float4*)(ep);
            float4 h1 = *(const float4*)(ep + 4);
            float4 h2 = *(const float4*)(ep + 8);
            float4 h3 = *(const float4*)(ep + 12);
            const float hv[16] = {h0.x,h0.y,h0.z,h0.w, h1.x,h1.y,h1.z,h1.w,
                                  h2.x,h2.y,h2.z,h2.w, h3.x,h3.y,h3.z,h3.w};
            #pragma unroll
            for (int j = 0; j < 16; j++) hsf[HIDX(u0 + j, b2)] = hv[j];
        }
        __syncthreads();

        // ---- P1: warp (rg,ksel): gh rows 6rg..6rg+5 + score row rg (h-part),
        //      batch-pair lanes, sub splits the k-quarter; Whh pre-dup'd ----
        {
            const int R = 6 * rg;
            const int kq = ksel * 128 + sub * 64;
            const u64* whhd = (const u64*)sm + (size_t)R * 256;   // dup'd rows
            const float* wah = Wah_s + rg * 256;
            u64 a0 = 0ull, a1 = 0ull, a2 = 0ull, a3 = 0ull, a4 = 0ull, a5 = 0ull, sacc = 0ull;
            #pragma unroll 2
            for (int i = 0; i < 32; i++) {
                int k = kq + 2 * i;
                u64 h0 = hs64[k * 17 + (k >> 4) + p];
                u64 h1 = hs64[(k + 1) * 17 + ((k + 1) >> 4) + p];
                ulonglong2 wv;
                wv = *(const ulonglong2*)(whhd + k);
                fma2(a0, wv.x, h0); fma2(a0, wv.y, h1);
                wv = *(const ulonglong2*)(whhd + 256 + k);
                fma2(a1, wv.x, h0); fma2(a1, wv.y, h1);
                wv = *(const ulonglong2*)(whhd + 512 + k);
                fma2(a2, wv.x, h0); fma2(a2, wv.y, h1);
                wv = *(const ulonglong2*)(whhd + 768 + k);
                fma2(a3, wv.x, h0); fma2(a3, wv.y, h1);
                wv = *(const ulonglong2*)(whhd + 1024 + k);
                fma2(a4, wv.x, h0); fma2(a4, wv.y, h1);
                wv = *(const ulonglong2*)(whhd + 1280 + k);
                fma2(a5, wv.x, h0); fma2(a5, wv.y, h1);
                float2 f = *(const float2*)(wah + k);
                fma2(sacc, dupf(f.x), h0); fma2(sacc, dupf(f.y), h1);
            }
            a0 = addf2(a0, shflx16(a0));
            a1 = addf2(a1, shflx16(a1));
            a2 = addf2(a2, shflx16(a2));
            a3 = addf2(a3, shflx16(a3));
            a4 = addf2(a4, shflx16(a4));
            a5 = addf2(a5, shflx16(a5));
            sacc = addf2(sacc, shflx16(sacc));
            if (sub == 0) {
                u64* gX = ksel ? ghsB64 : ghsA64;
                gX[(R + 0) * 17 + p] = a0;
                gX[(R + 1) * 17 + p] = a1;
                gX[(R + 2) * 17 + p] = a2;
                gX[(R + 3) * 17 + p] = a3;
                gX[(R + 4) * 17 + p] = a4;
                gX[(R + 5) * 17 + p] = a5;
                psc64[wrp * 16 + p] = sacc;
            }
        }
        __syncthreads();

        // ---- finalize scores: combine psc (h-part quarters) + psx (x-part) ----
        if (tid < 128) {
            int r = tid >> 4, pp = tid & 15;
            const float2* pc = (const float2*)psc64;
            const float2* px = (const float2*)psx64;
            float2 c0 = pc[(2 * r) * 16 + pp];
            float2 c1 = pc[(2 * r + 1) * 16 + pp];
            float2 x0 = px[(2 * r) * 16 + pp];
            float2 x1 = px[(2 * r + 1) * 16 + pp];
            float lo = c0.x + c1.x + x0.x + x1.x + ba_s[r];
            float hi = c0.y + c1.y + x0.y + x1.y + ba_s[r];
            __stcg(&d_scores[(gb0 + pp) * Iq + 8 * rr + r], ftanh(lo));
            __stcg(&d_scores[(gb0 + pp + 16) * Iq + 8 * rr + r], ftanh(hi));
        }
        // ---- scores barrier ----
        __syncthreads();
        if (tid == 0) { gb_arrive(grp, want); gb_wait(grp, want); }
        __syncthreads();

        // ---- P2: softmax + xw, 2 batches per warp ----
        #pragma unroll
        for (int bi = 0; bi < 2; bi++) {
            int b = 2 * wrp + bi;
            const float* sp = d_scores + (size_t)(gb0 + b) * Iq;
            float e0 = __expf(__ldcg(sp + lane));
            float e1 = __expf(__ldcg(sp + lane + 32));
            float e2 = __expf(__ldcg(sp + lane + 64));
            float e3 = __expf(__ldcg(sp + lane + 96));
            float s = e0 + e1 + e2 + e3;
            #pragma unroll
            for (int off = 16; off; off >>= 1) s += __shfl_xor_sync(0xffffffffu, s, off);
            float inv = 1.f / s;
            int k = lane;
            xwf[XIDX(k, b)] = e0 * inv * xtf[XIDX(k, b)];
            k = lane + 32;
            xwf[XIDX(k, b)] = e1 * inv * xtf[XIDX(k, b)];
            k = lane + 64;
            xwf[XIDX(k, b)] = e2 * inv * xtf[XIDX(k, b)];
            k = lane + 96;
            xwf[XIDX(k, b)] = e3 * inv * xtf[XIDX(k, b)];
        }
        __syncthreads();   // xw ready; all xtf(t) reads complete

        // ---- commit prefetched x(t+1); prefetch x(t+2) ----
        if (t + 1 < Sq) {
            const float v[8] = {pxa.x, pxa.y, pxa.z, pxa.w, pxb.x, pxb.y, pxb.z, pxb.w};
            #pragma unroll
            for (int j = 0; j < 8; j++) xtf[XIDX(pk + j, pb)] = v[j];
            if (t + 2 < Sq) {
                pxa = *(const float4*)(xrow + (size_t)(t + 2) * Iq);
                pxb = *(const float4*)(xrow + (size_t)(t + 2) * Iq + 4);
            }
        }

        // ---- P3: gi rows 6rg..6rg+5, batch-pair, sub splits k-quarter ----
        {
            const int R = 6 * rg;
            const int kq = ksel * 64 + sub * 32;
            const float* wih = Wih_s + R * 128;
            u64 c0 = 0ull, c1 = 0ull, c2 = 0ull, c3 = 0ull, c4 = 0ull, c5 = 0ull;
            #pragma unroll 2
            for (int i = 0; i < 16; i++) {
                int k = kq + 2 * i;
                u64 x0 = xw64[k * 17 + (k >> 3) + p];
                u64 x1 = xw64[(k + 1) * 17 + ((k + 1) >> 3) + p];
                float2 f;
                f = *(const float2*)(wih + k);
                fma2(c0, dupf(f.x), x0); fma2(c0, dupf(f.y), x1);
                f = *(const float2*)(wih + 128 + k);
                fma2(c1, dupf(f.x), x0); fma2(c1, dupf(f.y), x1);
                f = *(const float2*)(wih + 256 + k);
                fma2(c2, dupf(f.x), x0); fma2(c2, dupf(f.y), x1);
                f = *(const float2*)(wih + 384 + k);
                fma2(c3, dupf(f.x), x0); fma2(c3, dupf(f.y), x1);
                f = *(const float2*)(wih + 512 + k);
                fma2(c4, dupf(f.x), x0); fma2(c4, dupf(f.y), x1);
                f = *(const float2*)(wih + 640 + k);
                fma2(c5, dupf(f.x), x0); fma2(c5, dupf(f.y), x1);
            }
            c0 = addf2(c0, shflx16(c0));
            c1 = addf2(c1, shflx16(c1));
            c2 = addf2(c2, shflx16(c2));
            c3 = addf2(c3, shflx16(c3));
            c4 = addf2(c4, shflx16(c4));
            c5 = addf2(c5, shflx16(c5));
            if (sub == 0) {
                u64* gX = ksel ? gisB64 : gisA64;
                gX[(R + 0) * 17 + p] = c0;
                gX[(R + 1) * 17 + p] = c1;
                gX[(R + 2) * 17 + p] = c2;
                gX[(R + 3) * 17 + p] = c3;
                gX[(R + 4) * 17 + p] = c4;
                gX[(R + 5) * 17 + p] = c5;
            }
        }
        __syncthreads();

        // ---- gates + h_new ----
        {
            int u = tid & 15;
            int b = tid >> 4;
            int pq = b & 15, hb = b >> 4;
            #define GX(l) (((l) * 17 + pq) * 2 + hb)
            float gi_r = gisAf[GX(u)] + gisBf[GX(u)] + bih_s[u];
            float gh_r = ghsAf[GX(u)] + ghsBf[GX(u)] + bhh_s[u];
            float gi_z = gisAf[GX(16 + u)] + gisBf[GX(16 + u)] + bih_s[16 + u];
            float gh_z = ghsAf[GX(16 + u)] + ghsBf[GX(16 + u)] + bhh_s[16 + u];
            float gi_n = gisAf[GX(32 + u)] + gisBf[GX(32 + u)] + bih_s[32 + u];
            float gh_n = ghsAf[GX(32 + u)] + ghsBf[GX(32 + u)] + bhh_s[32 + u];
            #undef GX
            float r = fsig(gi_r + gh_r);
            float z = fsig(gi_z + gh_z);
            float n = ftanh(gi_n + r * gh_n);
            int ug = 16 * rr + u;
            float hp = hsf[HIDX(ug, b)];
            float hn = (1.f - z) * n + z * hp;
            d_enc[((size_t)t * Bq + gb0 + b) * Hq + ug] = hn;
        }
        // ---- h barrier with hidden work: psx(t+1) under the poll ----
        __syncthreads();
        if (tid == 0) gb_arrive(grp, want);
        if (t + 1 < Sq) {          // score x-part for t+1 (xtf already = x(t+1))
            const int kq = ksel * 64 + sub * 32;
            const float* wax = Wax_s + rg * 128;
            u64 xacc = 0ull;
            #pragma unroll 4
            for (int i = 0; i < 16; i++) {
                int k = kq + 2 * i;
                u64 x0 = xt64[k * 17 + (k >> 3) + p];
                u64 x1 = xt64[(k + 1) * 17 + ((k + 1) >> 3) + p];
                float2 f = *(const float2*)(wax + k);
                fma2(xacc, dupf(f.x), x0);
                fma2(xacc, dupf(f.y), x1);
            }
            xacc = addf2(xacc, shflx16(xacc));
            if (sub == 0) psx64[wrp * 16 + p] = xacc;
        }
        if (tid == 0) gb_wait(grp, want);
        __syncthreads();
    }

    // ================= temporal attention + FC (2 batches/CTA) =================
    float* wts = xtf;            // 256 floats (region reuse, linear)
    float* ess = gisAf;          // 512 floats
    float* prt = ghsAf;          // 512 floats
    if (tid < Hq) wts[tid] = W_t[tid];
    const float btv = b_t[0];
    const float bfv = b_f[0];
    __syncthreads();

    for (int bi = 0; bi < 2; bi++) {
        int bb = gb0 + 2 * rr + bi;

        for (int tt = wrp; tt < Sq; tt += 16) {
            const float* er = d_enc + ((size_t)tt * Bq + bb) * Hq;
            float s = 0.f;
            #pragma unroll
            for (int j = 0; j < 8; j++) s += er[lane + 32 * j] * wts[lane + 32 * j];
            #pragma unroll
            for (int off = 16; off; off >>= 1) s += __shfl_xor_sync(0xffffffffu, s, off);
            if (lane == 0) ess[tt] = __expf(ftanh(s + btv));
        }
        __syncthreads();

        float pp = ess[tid];
        #pragma unroll
        for (int off = 16; off; off >>= 1) pp += __shfl_xor_sync(0xffffffffu, pp, off);
        if (lane == 0) red[wrp] = pp;
        __syncthreads();
        float denom = 0.f;
        #pragma unroll
        for (int j = 0; j < 16; j++) denom += red[j];

        {
            int h = tid & 255, half = tid >> 8;
            const float* eb = d_enc + ((size_t)(half * 256) * Bq + bb) * Hq + h;
            const float* ep = ess + half * 256;
            float acc = 0.f;
            #pragma unroll 4
            for (int tt = 0; tt < 256; tt++)
                acc += ep[tt] * eb[(size_t)tt * Bq * Hq];
            prt[tid] = acc;
        }
        __syncthreads();

        if (tid < Hq) {
            float ctx = (prt[tid] + prt[tid + 256]) / denom;
            float part = ctx * W_f[tid];
            #pragma unroll
            for (int off = 16; off; off >>= 1) part += __shfl_xor_sync(0xffffffffu, part, off);
            if (lane == 0) red[16 + wrp] = part;
        }
        __syncthreads();
        if (tid == 0) {
            float lg = bfv;
            #pragma unroll
            for (int j = 0; j < 8; j++) lg += red[16 + j];
            out[bb] = 1.f / (1.f + __expf(-lg));
        }
        __syncthreads();
    }
}

extern "C" void kernel_launch(void* const* d_in, const int* in_sizes, int n_in,
                              void* d_out, int out_size)
{
    const float* x    = (const float*)d_in[0];
    const float* W_a  = (const float*)d_in[1];
    const float* b_a  = (const float*)d_in[2];
    const float* W_ih = (const float*)d_in[3];
    const float* b_ih = (const float*)d_in[4];
    const float* W_hh = (const float*)d_in[5];
    const float* b_hh = (const float*)d_in[6];
    const float* W_t  = (const float*)d_in[7];
    const float* b_t  = (const float*)d_in[8];
    const float* W_f  = (const float*)d_in[9];
    const float* b_f  = (const float*)d_in[10];

    const size_t smem_bytes = (size_t)SMEM_FLOATS * sizeof(float);   // 231840
    cudaFuncSetAttribute(da_rnn_kernel, cudaFuncAttributeMaxDynamicSharedMemorySize,
                         (int)smem_bytes);
    da_rnn_kernel<<<NCTA, NTHR, smem_bytes>>>(x, W_a, b_a, W_ih, b_ih, W_hh, b_hh,
                                              W_t, b_t, W_f, b_f, (float*)d_out);
}